// round 15
// baseline (speedup 1.0000x reference)
#include <cuda_runtime.h>
#include <cuda_fp16.h>
#include <mma.h>
#include <math.h>

using namespace nvcuda;

#define NN 100000
#define NPAD 100032      // 1563 * 64, padded row count for wmma tiles
#define DD 128
#define HH 64
#define CC 40
#define NB 391           // ceil(NN/256) scan blocks

typedef unsigned long long u64;

// ---- scratch (__device__ globals per harness rules) ----
__device__ __half g_xh[(size_t)NPAD * DD];    // x in fp16 (padded)   25.6 MB
__device__ __half g_w1h[128 * 128];           // [W1l | W1r] fp16
__device__ __half g_y1h[(size_t)NPAD * HH];   // x @ W1l   fp16       12.8 MB
__device__ __half g_selfh[(size_t)NPAD * HH]; // x @ W1r + b1 fp16    12.8 MB
__device__ __half g_hh[(size_t)NN * HH];      // layer-1 out fp16     12.8 MB
__device__ float  g_agg2[(size_t)NN * HH];    // mean(h[nbrs]) fp32   25.6 MB
__device__ int    g_cnt[NN];
__device__ int    g_rowptr[NN];
__device__ int    g_cur[NN];
__device__ float  g_invdeg[NN];
__device__ int    g_srcs[2000000];
__device__ int    g_exc[NB * 256];
__device__ int    g_bsum[512];
__device__ int    g_is64;

// ---- f32x2 packed-math helpers (sm_103a FFMA2) ----
__device__ __forceinline__ u64 pack2(float lo, float hi) {
    u64 r;
    asm("mov.b64 %0, {%1, %2};" : "=l"(r) : "f"(lo), "f"(hi));
    return r;
}
__device__ __forceinline__ void unpack2(u64 v, float& lo, float& hi) {
    asm("mov.b64 {%0, %1}, %2;" : "=f"(lo), "=f"(hi) : "l"(v));
}
__device__ __forceinline__ void fma2(u64& d, u64 a, u64 b) {
    asm("fma.rn.f32x2 %0, %1, %2, %0;" : "+l"(d) : "l"(a), "l"(b));
}

// ---------------------------------------------------------------------------
__global__ void k_detzero(const void* __restrict__ ei) {
    int i = blockIdx.x * blockDim.x + threadIdx.x;
    if (i < NN) g_cnt[i] = 0;
    if (blockIdx.x == 0) {
        if (threadIdx.x == 0) g_is64 = 1;
        __syncthreads();
        if (threadIdx.x < 128) {
            long long v = ((const long long*)ei)[threadIdx.x];
            if (v < 0 || v >= NN) atomicAnd(&g_is64, 0);
        }
    }
}

// convert x -> fp16 (padded rows zeroed)
__global__ void k_xh(const float* __restrict__ x) {
    int i = blockIdx.x * blockDim.x + threadIdx.x;   // half2 index
    if (i >= NPAD * DD / 2) return;
    __half2 v;
    if (i < NN * DD / 2) {
        float2 f = ((const float2*)x)[i];
        v = __floats2half2_rn(f.x, f.y);
    } else {
        v = __floats2half2_rn(0.f, 0.f);
    }
    ((__half2*)g_xh)[i] = v;
}

// convert [W1l | W1r] -> fp16 combined 128x128
__global__ void k_wh(const float* __restrict__ Wl, const float* __restrict__ Wr) {
    int i = blockIdx.x * blockDim.x + threadIdx.x;
    if (i >= 128 * 128) return;
    int krow = i >> 7, col = i & 127;
    float v = (col < 64) ? Wl[krow * 64 + col] : Wr[krow * 64 + (col - 64)];
    g_w1h[i] = __float2half_rn(v);
}

__global__ void k_hist(const void* __restrict__ ei, int nE) {
    int e = blockIdx.x * blockDim.x + threadIdx.x;
    if (e >= nE) return;
    int d = g_is64 ? (int)((const long long*)ei)[nE + e]
                   : ((const int*)ei)[nE + e];
    atomicAdd(&g_cnt[d], 1);
}

__global__ void k_scan1() {
    __shared__ int sh[256];
    int t = threadIdx.x, b = blockIdx.x;
    int i = b * 256 + t;
    int v = (i < NN) ? g_cnt[i] : 0;
    sh[t] = v;
    __syncthreads();
    #pragma unroll
    for (int off = 1; off < 256; off <<= 1) {
        int u = (t >= off) ? sh[t - off] : 0;
        __syncthreads();
        sh[t] += u;
        __syncthreads();
    }
    if (i < NN) g_exc[i] = sh[t] - v;
    if (t == 255) g_bsum[b] = sh[t];
}

__global__ void k_scan23() {
    __shared__ int red[8];
    __shared__ int boff;
    int b = blockIdx.x, t = threadIdx.x;
    int v = 0;
    if (t < b) v = g_bsum[t];
    if (t + 256 < b) v += g_bsum[t + 256];
    #pragma unroll
    for (int o = 16; o; o >>= 1) v += __shfl_xor_sync(0xffffffffu, v, o);
    if ((t & 31) == 0) red[t >> 5] = v;
    __syncthreads();
    if (t == 0) {
        int s = 0;
        #pragma unroll
        for (int j = 0; j < 8; ++j) s += red[j];
        boff = s;
    }
    __syncthreads();
    int i = b * 256 + t;
    if (i < NN) {
        int row = g_exc[i] + boff;
        g_rowptr[i] = row;
        g_cur[i] = row;
        g_invdeg[i] = 1.0f / fmaxf((float)g_cnt[i], 1.0f);
    }
}

__global__ void k_fill(const void* __restrict__ ei, int nE) {
    int e = blockIdx.x * blockDim.x + threadIdx.x;
    if (e >= nE) return;
    int s, d;
    if (g_is64) {
        const long long* p = (const long long*)ei;
        s = (int)p[e]; d = (int)p[nE + e];
    } else {
        const int* p = (const int*)ei;
        s = p[e]; d = p[nE + e];
    }
    int pos = atomicAdd(&g_cur[d], 1);
    g_srcs[pos] = s;
}

// ---------------------------------------------------------------------------
// GEMM1 via wmma (HMMA tensor cores): [y1 | self+b1] = xh @ w1h, fp32 accum.
// Block: 256 threads = 8 warps, tile 64 rows x 128 cols.
// Warp w: rows (blk*64 + (w&3)*16 .. +15), cols (w>>2)*64 .. +63 (4 frags).
// A/B fragments loaded straight from global (L1/L2-resident). Accums staged
// per-warp in smem, then bias + fp16 epilogue. No __syncthreads needed.
// ---------------------------------------------------------------------------
__global__ void __launch_bounds__(256)
k_gemm1(const float* __restrict__ b) {
    __shared__ float stage[8][16 * 64];   // 32 KB, one 16x64 region per warp

    int w = threadIdx.x >> 5;
    int lane = threadIdx.x & 31;
    int warpRow = w & 3;
    int warpColHalf = w >> 2;             // 0: y1 cols, 1: self cols
    int rowBase = blockIdx.x * 64 + warpRow * 16;
    int colBase = warpColHalf * 64;

    wmma::fragment<wmma::accumulator, 16, 16, 16, float> c[4];
    #pragma unroll
    for (int j = 0; j < 4; ++j) wmma::fill_fragment(c[j], 0.0f);

    const __half* xrow = g_xh + (size_t)rowBase * DD;
    #pragma unroll 1
    for (int k = 0; k < 128; k += 16) {
        wmma::fragment<wmma::matrix_a, 16, 16, 16, __half, wmma::row_major> a;
        wmma::load_matrix_sync(a, xrow + k, DD);
        #pragma unroll
        for (int j = 0; j < 4; ++j) {
            wmma::fragment<wmma::matrix_b, 16, 16, 16, __half, wmma::row_major> bf;
            wmma::load_matrix_sync(bf, g_w1h + k * 128 + colBase + j * 16, 128);
            wmma::mma_sync(c[j], a, bf, c[j]);
        }
    }

    #pragma unroll
    for (int j = 0; j < 4; ++j)
        wmma::store_matrix_sync(&stage[w][j * 16], c[j], 64, wmma::mem_row_major);
    __syncwarp();

    // epilogue: lane covers row r = lane>>1, cols ch..ch+31 of the 64-col half
    int r = lane >> 1;
    int ch = (lane & 1) * 32;
    int grow = rowBase + r;
    __half* dst = warpColHalf ? g_selfh : g_y1h;
    const float* bp = b;
    if (grow < NN) {
        #pragma unroll
        for (int cc = 0; cc < 32; cc += 2) {
            int col = ch + cc;
            float v0 = stage[w][r * 64 + col];
            float v1 = stage[w][r * 64 + col + 1];
            if (warpColHalf) {
                v0 += bp[col];
                v1 += bp[col + 1];
            }
            *(__half2*)(dst + (size_t)grow * HH + col) = __floats2half2_rn(v0, v1);
        }
    }
}

// ---------------------------------------------------------------------------
// agg1 + ReLU: h[n] = relu( invdeg * sum_{s} y1[s] + self[n] )
// warp per node, half2 lanes, fp32 accumulation.  (r14 measured version)
// ---------------------------------------------------------------------------
__global__ void k_agg1(void) {
    int w = (blockIdx.x * blockDim.x + threadIdx.x) >> 5;
    int lane = threadIdx.x & 31;
    if (w >= NN) return;
    int beg = g_rowptr[w], n = g_cnt[w];
    const __half2* yb = (const __half2*)g_y1h;
    float2 a0 = make_float2(0.f, 0.f), a1 = make_float2(0.f, 0.f);
    int e = 0;
    for (; e + 1 < n; e += 2) {
        int s0 = g_srcs[beg + e];
        int s1 = g_srcs[beg + e + 1];
        float2 v0 = __half22float2(__ldg(yb + (size_t)s0 * 32 + lane));
        float2 v1 = __half22float2(__ldg(yb + (size_t)s1 * 32 + lane));
        a0.x += v0.x; a0.y += v0.y;
        a1.x += v1.x; a1.y += v1.y;
    }
    if (e < n) {
        int s0 = g_srcs[beg + e];
        float2 v0 = __half22float2(__ldg(yb + (size_t)s0 * 32 + lane));
        a0.x += v0.x; a0.y += v0.y;
    }
    float sc = g_invdeg[w];
    float2 s = __half22float2(((const __half2*)g_selfh)[(size_t)w * 32 + lane]);
    float2 o;
    o.x = fmaxf((a0.x + a1.x) * sc + s.x, 0.f);
    o.y = fmaxf((a0.y + a1.y) * sc + s.y, 0.f);
    ((__half2*)g_hh)[(size_t)w * 32 + lane] = __float22half2_rn(o);
}

// ---------------------------------------------------------------------------
// agg2: g_agg2[n] = invdeg * sum_{s} h[s]   (half2 gather, fp32 out)
// ---------------------------------------------------------------------------
__global__ void k_agg2(void) {
    int w = (blockIdx.x * blockDim.x + threadIdx.x) >> 5;
    int lane = threadIdx.x & 31;
    if (w >= NN) return;
    int beg = g_rowptr[w], n = g_cnt[w];
    const __half2* hb = (const __half2*)g_hh;
    float2 a0 = make_float2(0.f, 0.f), a1 = make_float2(0.f, 0.f);
    int e = 0;
    for (; e + 1 < n; e += 2) {
        int s0 = g_srcs[beg + e];
        int s1 = g_srcs[beg + e + 1];
        float2 v0 = __half22float2(__ldg(hb + (size_t)s0 * 32 + lane));
        float2 v1 = __half22float2(__ldg(hb + (size_t)s1 * 32 + lane));
        a0.x += v0.x; a0.y += v0.y;
        a1.x += v1.x; a1.y += v1.y;
    }
    if (e < n) {
        int s0 = g_srcs[beg + e];
        float2 v0 = __half22float2(__ldg(hb + (size_t)s0 * 32 + lane));
        a0.x += v0.x; a0.y += v0.y;
    }
    float sc = g_invdeg[w];
    float2 o;
    o.x = (a0.x + a1.x) * sc;
    o.y = (a0.y + a1.y) * sc;
    ((float2*)g_agg2)[(size_t)w * 32 + lane] = o;
}

// ---------------------------------------------------------------------------
// GEMM2 + fused log_softmax, persistent grid-stride, packed f32x2.
// (r14 measured version)
// ---------------------------------------------------------------------------
__global__ void __launch_bounds__(256)
k_gemm2(const float* __restrict__ Wl,
        const float* __restrict__ Wr,
        const float* __restrict__ b,
        float* __restrict__ out) {
    __shared__ float2 sW[64 * 40];
    __shared__ float sb[40];
    int tid = threadIdx.x;
    for (int i = tid; i < 64 * 40; i += blockDim.x)
        sW[i] = make_float2(Wl[i], Wr[i]);
    if (tid < 40) sb[tid] = b[tid];
    __syncthreads();

    int lane = tid & 31;
    bool lo8 = (lane < 8);
    int gwarp = (blockIdx.x * blockDim.x + tid) >> 5;
    int nwarps = (gridDim.x * blockDim.x) >> 5;

    for (int w = gwarp; w < NN; w += nwarps) {
        const float* ag = g_agg2 + (size_t)w * HH;
        float a0 = ag[lane], a1 = ag[lane + 32];
        float2 hf = __half22float2(((const __half2*)g_hh)[(size_t)w * 32 + lane]);
        float hlo = hf.x, hhi = hf.y;   // features 2*lane, 2*lane+1

        u64 acc0 = 0, acc1 = 0;
        #pragma unroll
        for (int f = 0; f < 64; ++f) {
            float av = __shfl_sync(0xffffffffu, (f < 32) ? a0 : a1, f & 31);
            float hv = __shfl_sync(0xffffffffu, (f & 1) ? hhi : hlo, f >> 1);
            u64 p = pack2(av, hv);
            fma2(acc0, p, *(const u64*)&sW[f * 40 + lane]);
            if (lo8) fma2(acc1, p, *(const u64*)&sW[f * 40 + 32 + lane]);
        }

        float u0, v0, u1, v1;
        unpack2(acc0, u0, v0);
        unpack2(acc1, u1, v1);
        float z0 = u0 + v0 + sb[lane];
        float z1 = lo8 ? (u1 + v1 + sb[32 + lane]) : -INFINITY;

        float m = fmaxf(z0, z1);
        #pragma unroll
        for (int o = 16; o; o >>= 1) m = fmaxf(m, __shfl_xor_sync(0xffffffffu, m, o));
        float e = expf(z0 - m) + (lo8 ? expf(z1 - m) : 0.f);
        #pragma unroll
        for (int o = 16; o; o >>= 1) e += __shfl_xor_sync(0xffffffffu, e, o);
        float lse = logf(e) + m;

        out[(size_t)w * CC + lane] = z0 - lse;
        if (lo8) out[(size_t)w * CC + 32 + lane] = z1 - lse;
    }
}

// ---------------------------------------------------------------------------
extern "C" void kernel_launch(void* const* d_in, const int* in_sizes, int n_in,
                              void* d_out, int out_size) {
    const float* x   = (const float*)d_in[0];
    const void*  ei  = d_in[1];
    const float* W1l = (const float*)d_in[2];
    const float* W1r = (const float*)d_in[3];
    const float* b1  = (const float*)d_in[4];
    const float* W2l = (const float*)d_in[5];
    const float* W2r = (const float*)d_in[6];
    const float* b2  = (const float*)d_in[7];
    float* out = (float*)d_out;

    int nE = in_sizes[1] / 2;
    int eBlocks = (nE + 255) / 256;
    int nWarpBlocks = (NN * 32 + 255) / 256;
    int xhBlocks = (NPAD * DD / 2 + 255) / 256;

    k_detzero<<<(NN + 255) / 256, 256>>>(ei);            // 1
    k_xh<<<xhBlocks, 256>>>(x);                          // 2
    k_wh<<<64, 256>>>(W1l, W1r);                         // 3
    k_gemm1<<<NPAD / 64, 256>>>(b1);                     // 4 <- ncu window
    k_hist<<<eBlocks, 256>>>(ei, nE);                    // 5
    k_scan1<<<NB, 256>>>();                              // 6
    k_scan23<<<NB, 256>>>();                             // 7
    k_fill<<<eBlocks, 256>>>(ei, nE);                    // 8
    k_agg1<<<nWarpBlocks, 256>>>();                      // 9
    k_agg2<<<nWarpBlocks, 256>>>();                      // 10
    k_gemm2<<<1184, 256>>>(W2l, W2r, b2, out);           // 11 persistent
}

// round 16
// speedup vs baseline: 1.1207x; 1.1207x over previous
#include <cuda_runtime.h>
#include <cuda_fp16.h>
#include <mma.h>
#include <math.h>

using namespace nvcuda;

#define NN 100000
#define NPAD 100032      // 1563 * 64, padded row count for wmma tiles
#define DD 128
#define HH 64
#define CC 40
#define NB 391           // ceil(NN/256) scan blocks

typedef unsigned long long u64;

// ---- scratch (__device__ globals per harness rules) ----
__device__ __half g_xh[(size_t)NPAD * DD];    // x in fp16 (padded)   25.6 MB
__device__ __half g_w1h[128 * 128];           // [W1l | W1r] fp16
__device__ __half g_y1h[(size_t)NPAD * HH];   // x @ W1l   fp16       12.8 MB
__device__ __half g_selfh[(size_t)NPAD * HH]; // x @ W1r + b1 fp16    12.8 MB
__device__ __half g_hh[(size_t)NN * HH];      // layer-1 out fp16     12.8 MB
__device__ float  g_agg2[(size_t)NN * HH];    // mean(h[nbrs]) fp32   25.6 MB
__device__ int    g_cnt[NN];
__device__ int    g_rowptr[NN];
__device__ int    g_cur[NN];
__device__ float  g_invdeg[NN];
__device__ int    g_srcs[2000000];
__device__ int    g_exc[NB * 256];
__device__ int    g_bsum[512];
__device__ int    g_is64;

// ---- f32x2 packed-math helpers (sm_103a FFMA2) ----
__device__ __forceinline__ u64 pack2(float lo, float hi) {
    u64 r;
    asm("mov.b64 %0, {%1, %2};" : "=l"(r) : "f"(lo), "f"(hi));
    return r;
}
__device__ __forceinline__ void unpack2(u64 v, float& lo, float& hi) {
    asm("mov.b64 {%0, %1}, %2;" : "=f"(lo), "=f"(hi) : "l"(v));
}
__device__ __forceinline__ void fma2(u64& d, u64 a, u64 b) {
    asm("fma.rn.f32x2 %0, %1, %2, %0;" : "+l"(d) : "l"(a), "l"(b));
}

// ---------------------------------------------------------------------------
__global__ void k_detzero(const void* __restrict__ ei) {
    int i = blockIdx.x * blockDim.x + threadIdx.x;
    if (i < NN) g_cnt[i] = 0;
    if (blockIdx.x == 0) {
        if (threadIdx.x == 0) g_is64 = 1;
        __syncthreads();
        if (threadIdx.x < 128) {
            long long v = ((const long long*)ei)[threadIdx.x];
            if (v < 0 || v >= NN) atomicAnd(&g_is64, 0);
        }
    }
}

// convert x -> fp16 (padded rows zeroed)
__global__ void k_xh(const float* __restrict__ x) {
    int i = blockIdx.x * blockDim.x + threadIdx.x;   // half2 index
    if (i >= NPAD * DD / 2) return;
    __half2 v;
    if (i < NN * DD / 2) {
        float2 f = ((const float2*)x)[i];
        v = __floats2half2_rn(f.x, f.y);
    } else {
        v = __floats2half2_rn(0.f, 0.f);
    }
    ((__half2*)g_xh)[i] = v;
}

// convert [W1l | W1r] -> fp16 combined 128x128
__global__ void k_wh(const float* __restrict__ Wl, const float* __restrict__ Wr) {
    int i = blockIdx.x * blockDim.x + threadIdx.x;
    if (i >= 128 * 128) return;
    int krow = i >> 7, col = i & 127;
    float v = (col < 64) ? Wl[krow * 64 + col] : Wr[krow * 64 + (col - 64)];
    g_w1h[i] = __float2half_rn(v);
}

__global__ void k_hist(const void* __restrict__ ei, int nE) {
    int e = blockIdx.x * blockDim.x + threadIdx.x;
    if (e >= nE) return;
    int d = g_is64 ? (int)((const long long*)ei)[nE + e]
                   : ((const int*)ei)[nE + e];
    atomicAdd(&g_cnt[d], 1);
}

__global__ void k_scan1() {
    __shared__ int sh[256];
    int t = threadIdx.x, b = blockIdx.x;
    int i = b * 256 + t;
    int v = (i < NN) ? g_cnt[i] : 0;
    sh[t] = v;
    __syncthreads();
    #pragma unroll
    for (int off = 1; off < 256; off <<= 1) {
        int u = (t >= off) ? sh[t - off] : 0;
        __syncthreads();
        sh[t] += u;
        __syncthreads();
    }
    if (i < NN) g_exc[i] = sh[t] - v;
    if (t == 255) g_bsum[b] = sh[t];
}

__global__ void k_scan23() {
    __shared__ int red[8];
    __shared__ int boff;
    int b = blockIdx.x, t = threadIdx.x;
    int v = 0;
    if (t < b) v = g_bsum[t];
    if (t + 256 < b) v += g_bsum[t + 256];
    #pragma unroll
    for (int o = 16; o; o >>= 1) v += __shfl_xor_sync(0xffffffffu, v, o);
    if ((t & 31) == 0) red[t >> 5] = v;
    __syncthreads();
    if (t == 0) {
        int s = 0;
        #pragma unroll
        for (int j = 0; j < 8; ++j) s += red[j];
        boff = s;
    }
    __syncthreads();
    int i = b * 256 + t;
    if (i < NN) {
        int row = g_exc[i] + boff;
        g_rowptr[i] = row;
        g_cur[i] = row;
        g_invdeg[i] = 1.0f / fmaxf((float)g_cnt[i], 1.0f);
    }
}

__global__ void k_fill(const void* __restrict__ ei, int nE) {
    int e = blockIdx.x * blockDim.x + threadIdx.x;
    if (e >= nE) return;
    int s, d;
    if (g_is64) {
        const long long* p = (const long long*)ei;
        s = (int)p[e]; d = (int)p[nE + e];
    } else {
        const int* p = (const int*)ei;
        s = p[e]; d = p[nE + e];
    }
    int pos = atomicAdd(&g_cur[d], 1);
    g_srcs[pos] = s;
}

// ---------------------------------------------------------------------------
// GEMM1 via wmma v2: W staged in smem (loaded ONCE per block), B fragments
// from smem; A fragments from global (L1-resident). After compute, the W
// smem region is REUSED as the fp32 epilogue staging buffer.
// Block: 256 threads = 8 warps, tile 64 rows x 128 cols.
// ---------------------------------------------------------------------------
#define WPITCH 136   // half pitch (mult. of 8 for wmma ldm)

__global__ void __launch_bounds__(256)
k_gemm1(const float* __restrict__ b) {
    __shared__ __align__(16) __half Wm[128 * WPITCH];  // 34.8 KB

    int tid = threadIdx.x;
    int w = tid >> 5;
    int lane = tid & 31;
    int warpRow = w & 3;
    int warpColHalf = w >> 2;             // 0: y1 cols, 1: self cols
    int rowBase = blockIdx.x * 64 + warpRow * 16;
    int colBase = warpColHalf * 64;

    // cooperative load of W (128x128 halfs) into padded smem, half2 moves
    {
        const __half2* src = (const __half2*)g_w1h;
        for (int i = tid; i < 128 * 64; i += 256) {
            int row = i >> 6;
            int c2 = i & 63;
            *(__half2*)&Wm[row * WPITCH + c2 * 2] = src[row * 64 + c2];
        }
    }
    __syncthreads();

    wmma::fragment<wmma::accumulator, 16, 16, 16, float> c[4];
    #pragma unroll
    for (int j = 0; j < 4; ++j) wmma::fill_fragment(c[j], 0.0f);

    const __half* xrow = g_xh + (size_t)rowBase * DD;
    #pragma unroll 1
    for (int k = 0; k < 128; k += 16) {
        wmma::fragment<wmma::matrix_a, 16, 16, 16, __half, wmma::row_major> a;
        wmma::load_matrix_sync(a, xrow + k, DD);
        #pragma unroll
        for (int j = 0; j < 4; ++j) {
            wmma::fragment<wmma::matrix_b, 16, 16, 16, __half, wmma::row_major> bf;
            wmma::load_matrix_sync(bf, &Wm[k * WPITCH + colBase + j * 16], WPITCH);
            wmma::mma_sync(c[j], a, bf, c[j]);
        }
    }
    __syncthreads();   // everyone done reading W; reuse smem as stage

    float* stage = (float*)Wm;            // 8 warps x 16x64 fp32 = 32 KB
    float* mystage = stage + w * 16 * 64;
    #pragma unroll
    for (int j = 0; j < 4; ++j)
        wmma::store_matrix_sync(mystage + j * 16, c[j], 64, wmma::mem_row_major);
    __syncwarp();

    // epilogue: lane covers row r = lane>>1, cols ch..ch+31 of the 64-col half
    int r = lane >> 1;
    int ch = (lane & 1) * 32;
    int grow = rowBase + r;
    __half* dst = warpColHalf ? g_selfh : g_y1h;
    if (grow < NN) {
        #pragma unroll
        for (int cc = 0; cc < 32; cc += 2) {
            int col = ch + cc;
            float v0 = mystage[r * 64 + col];
            float v1 = mystage[r * 64 + col + 1];
            if (warpColHalf) {
                v0 += b[col];
                v1 += b[col + 1];
            }
            *(__half2*)(dst + (size_t)grow * HH + col) = __floats2half2_rn(v0, v1);
        }
    }
}

// ---------------------------------------------------------------------------
// agg1 + ReLU: h[n] = relu( invdeg * sum_{s} y1[s] + self[n] )
// warp per node, half2 lanes, fp32 accumulation.  (measured version)
// ---------------------------------------------------------------------------
__global__ void k_agg1(void) {
    int w = (blockIdx.x * blockDim.x + threadIdx.x) >> 5;
    int lane = threadIdx.x & 31;
    if (w >= NN) return;
    int beg = g_rowptr[w], n = g_cnt[w];
    const __half2* yb = (const __half2*)g_y1h;
    float2 a0 = make_float2(0.f, 0.f), a1 = make_float2(0.f, 0.f);
    int e = 0;
    for (; e + 1 < n; e += 2) {
        int s0 = g_srcs[beg + e];
        int s1 = g_srcs[beg + e + 1];
        float2 v0 = __half22float2(__ldg(yb + (size_t)s0 * 32 + lane));
        float2 v1 = __half22float2(__ldg(yb + (size_t)s1 * 32 + lane));
        a0.x += v0.x; a0.y += v0.y;
        a1.x += v1.x; a1.y += v1.y;
    }
    if (e < n) {
        int s0 = g_srcs[beg + e];
        float2 v0 = __half22float2(__ldg(yb + (size_t)s0 * 32 + lane));
        a0.x += v0.x; a0.y += v0.y;
    }
    float sc = g_invdeg[w];
    float2 s = __half22float2(((const __half2*)g_selfh)[(size_t)w * 32 + lane]);
    float2 o;
    o.x = fmaxf((a0.x + a1.x) * sc + s.x, 0.f);
    o.y = fmaxf((a0.y + a1.y) * sc + s.y, 0.f);
    ((__half2*)g_hh)[(size_t)w * 32 + lane] = __float22half2_rn(o);
}

// ---------------------------------------------------------------------------
// agg2: g_agg2[n] = invdeg * sum_{s} h[s]   (half2 gather, fp32 out)
// ---------------------------------------------------------------------------
__global__ void k_agg2(void) {
    int w = (blockIdx.x * blockDim.x + threadIdx.x) >> 5;
    int lane = threadIdx.x & 31;
    if (w >= NN) return;
    int beg = g_rowptr[w], n = g_cnt[w];
    const __half2* hb = (const __half2*)g_hh;
    float2 a0 = make_float2(0.f, 0.f), a1 = make_float2(0.f, 0.f);
    int e = 0;
    for (; e + 1 < n; e += 2) {
        int s0 = g_srcs[beg + e];
        int s1 = g_srcs[beg + e + 1];
        float2 v0 = __half22float2(__ldg(hb + (size_t)s0 * 32 + lane));
        float2 v1 = __half22float2(__ldg(hb + (size_t)s1 * 32 + lane));
        a0.x += v0.x; a0.y += v0.y;
        a1.x += v1.x; a1.y += v1.y;
    }
    if (e < n) {
        int s0 = g_srcs[beg + e];
        float2 v0 = __half22float2(__ldg(hb + (size_t)s0 * 32 + lane));
        a0.x += v0.x; a0.y += v0.y;
    }
    float sc = g_invdeg[w];
    float2 o;
    o.x = (a0.x + a1.x) * sc;
    o.y = (a0.y + a1.y) * sc;
    ((float2*)g_agg2)[(size_t)w * 32 + lane] = o;
}

// ---------------------------------------------------------------------------
// GEMM2 + fused log_softmax, persistent grid-stride, packed f32x2.
// (measured version)
// ---------------------------------------------------------------------------
__global__ void __launch_bounds__(256)
k_gemm2(const float* __restrict__ Wl,
        const float* __restrict__ Wr,
        const float* __restrict__ b,
        float* __restrict__ out) {
    __shared__ float2 sW[64 * 40];
    __shared__ float sb[40];
    int tid = threadIdx.x;
    for (int i = tid; i < 64 * 40; i += blockDim.x)
        sW[i] = make_float2(Wl[i], Wr[i]);
    if (tid < 40) sb[tid] = b[tid];
    __syncthreads();

    int lane = tid & 31;
    bool lo8 = (lane < 8);
    int gwarp = (blockIdx.x * blockDim.x + tid) >> 5;
    int nwarps = (gridDim.x * blockDim.x) >> 5;

    for (int w = gwarp; w < NN; w += nwarps) {
        const float* ag = g_agg2 + (size_t)w * HH;
        float a0 = ag[lane], a1 = ag[lane + 32];
        float2 hf = __half22float2(((const __half2*)g_hh)[(size_t)w * 32 + lane]);
        float hlo = hf.x, hhi = hf.y;   // features 2*lane, 2*lane+1

        u64 acc0 = 0, acc1 = 0;
        #pragma unroll
        for (int f = 0; f < 64; ++f) {
            float av = __shfl_sync(0xffffffffu, (f < 32) ? a0 : a1, f & 31);
            float hv = __shfl_sync(0xffffffffu, (f & 1) ? hhi : hlo, f >> 1);
            u64 p = pack2(av, hv);
            fma2(acc0, p, *(const u64*)&sW[f * 40 + lane]);
            if (lo8) fma2(acc1, p, *(const u64*)&sW[f * 40 + 32 + lane]);
        }

        float u0, v0, u1, v1;
        unpack2(acc0, u0, v0);
        unpack2(acc1, u1, v1);
        float z0 = u0 + v0 + sb[lane];
        float z1 = lo8 ? (u1 + v1 + sb[32 + lane]) : -INFINITY;

        float m = fmaxf(z0, z1);
        #pragma unroll
        for (int o = 16; o; o >>= 1) m = fmaxf(m, __shfl_xor_sync(0xffffffffu, m, o));
        float e = expf(z0 - m) + (lo8 ? expf(z1 - m) : 0.f);
        #pragma unroll
        for (int o = 16; o; o >>= 1) e += __shfl_xor_sync(0xffffffffu, e, o);
        float lse = logf(e) + m;

        out[(size_t)w * CC + lane] = z0 - lse;
        if (lo8) out[(size_t)w * CC + 32 + lane] = z1 - lse;
    }
}

// ---------------------------------------------------------------------------
extern "C" void kernel_launch(void* const* d_in, const int* in_sizes, int n_in,
                              void* d_out, int out_size) {
    const float* x   = (const float*)d_in[0];
    const void*  ei  = d_in[1];
    const float* W1l = (const float*)d_in[2];
    const float* W1r = (const float*)d_in[3];
    const float* b1  = (const float*)d_in[4];
    const float* W2l = (const float*)d_in[5];
    const float* W2r = (const float*)d_in[6];
    const float* b2  = (const float*)d_in[7];
    float* out = (float*)d_out;

    int nE = in_sizes[1] / 2;
    int eBlocks = (nE + 255) / 256;
    int nWarpBlocks = (NN * 32 + 255) / 256;
    int xhBlocks = (NPAD * DD / 2 + 255) / 256;

    k_detzero<<<(NN + 255) / 256, 256>>>(ei);            // 1
    k_xh<<<xhBlocks, 256>>>(x);                          // 2
    k_wh<<<64, 256>>>(W1l, W1r);                         // 3
    k_gemm1<<<NPAD / 64, 256>>>(b1);                     // 4 <- ncu window
    k_hist<<<eBlocks, 256>>>(ei, nE);                    // 5
    k_scan1<<<NB, 256>>>();                              // 6
    k_scan23<<<NB, 256>>>();                             // 7
    k_fill<<<eBlocks, 256>>>(ei, nE);                    // 8
    k_agg1<<<nWarpBlocks, 256>>>();                      // 9
    k_agg2<<<nWarpBlocks, 256>>>();                      // 10
    k_gemm2<<<1184, 256>>>(W2l, W2r, b2, out);           // 11 persistent
}

// round 17
// speedup vs baseline: 1.1774x; 1.0506x over previous
#include <cuda_runtime.h>
#include <cuda_fp16.h>
#include <mma.h>
#include <math.h>

using namespace nvcuda;

#define NN 100000
#define NPAD 100032      // 1563 * 64
#define DD 128
#define HH 64
#define CC 40
#define NB 391           // ceil(NN/256) scan blocks

typedef unsigned long long u64;

// ---- scratch (__device__ globals per harness rules) ----
__device__ __half g_w1h[128 * 128];           // [W1l | W1r] fp16
__device__ __half g_y1h[(size_t)NPAD * HH];   // x @ W1l   fp16       12.8 MB
__device__ __half g_selfh[(size_t)NPAD * HH]; // x @ W1r + b1 fp16    12.8 MB
__device__ __half g_hh[(size_t)NN * HH];      // layer-1 out fp16     12.8 MB
__device__ float  g_agg2[(size_t)NN * HH];    // mean(h[nbrs]) fp32   25.6 MB
__device__ int    g_cnt[NN];
__device__ int    g_rowptr[NN];
__device__ int    g_cur[NN];
__device__ float  g_invdeg[NN];
__device__ int    g_srcs[2000000];
__device__ int    g_exc[NB * 256];
__device__ int    g_bsum[512];
__device__ int    g_is64;

// ---- f32x2 packed-math helpers (sm_103a FFMA2) ----
__device__ __forceinline__ u64 pack2(float lo, float hi) {
    u64 r;
    asm("mov.b64 %0, {%1, %2};" : "=l"(r) : "f"(lo), "f"(hi));
    return r;
}
__device__ __forceinline__ void unpack2(u64 v, float& lo, float& hi) {
    asm("mov.b64 {%0, %1}, %2;" : "=f"(lo), "=f"(hi) : "l"(v));
}
__device__ __forceinline__ void fma2(u64& d, u64 a, u64 b) {
    asm("fma.rn.f32x2 %0, %1, %2, %0;" : "+l"(d) : "l"(a), "l"(b));
}

// ---------------------------------------------------------------------------
__global__ void k_detzero(const void* __restrict__ ei) {
    int i = blockIdx.x * blockDim.x + threadIdx.x;
    if (i < NN) g_cnt[i] = 0;
    if (blockIdx.x == 0) {
        if (threadIdx.x == 0) g_is64 = 1;
        __syncthreads();
        if (threadIdx.x < 128) {
            long long v = ((const long long*)ei)[threadIdx.x];
            if (v < 0 || v >= NN) atomicAnd(&g_is64, 0);
        }
    }
}

// convert [W1l | W1r] -> fp16 combined 128x128
__global__ void k_wh(const float* __restrict__ Wl, const float* __restrict__ Wr) {
    int i = blockIdx.x * blockDim.x + threadIdx.x;
    if (i >= 128 * 128) return;
    int krow = i >> 7, col = i & 127;
    float v = (col < 64) ? Wl[krow * 64 + col] : Wr[krow * 64 + (col - 64)];
    g_w1h[i] = __float2half_rn(v);
}

__global__ void k_hist(const void* __restrict__ ei, int nE) {
    int e = blockIdx.x * blockDim.x + threadIdx.x;
    if (e >= nE) return;
    int d = g_is64 ? (int)((const long long*)ei)[nE + e]
                   : ((const int*)ei)[nE + e];
    atomicAdd(&g_cnt[d], 1);
}

__global__ void k_scan1() {
    __shared__ int sh[256];
    int t = threadIdx.x, b = blockIdx.x;
    int i = b * 256 + t;
    int v = (i < NN) ? g_cnt[i] : 0;
    sh[t] = v;
    __syncthreads();
    #pragma unroll
    for (int off = 1; off < 256; off <<= 1) {
        int u = (t >= off) ? sh[t - off] : 0;
        __syncthreads();
        sh[t] += u;
        __syncthreads();
    }
    if (i < NN) g_exc[i] = sh[t] - v;
    if (t == 255) g_bsum[b] = sh[t];
}

__global__ void k_scan23() {
    __shared__ int red[8];
    __shared__ int boff;
    int b = blockIdx.x, t = threadIdx.x;
    int v = 0;
    if (t < b) v = g_bsum[t];
    if (t + 256 < b) v += g_bsum[t + 256];
    #pragma unroll
    for (int o = 16; o; o >>= 1) v += __shfl_xor_sync(0xffffffffu, v, o);
    if ((t & 31) == 0) red[t >> 5] = v;
    __syncthreads();
    if (t == 0) {
        int s = 0;
        #pragma unroll
        for (int j = 0; j < 8; ++j) s += red[j];
        boff = s;
    }
    __syncthreads();
    int i = b * 256 + t;
    if (i < NN) {
        int row = g_exc[i] + boff;
        g_rowptr[i] = row;
        g_cur[i] = row;
        g_invdeg[i] = 1.0f / fmaxf((float)g_cnt[i], 1.0f);
    }
}

__global__ void k_fill(const void* __restrict__ ei, int nE) {
    int e = blockIdx.x * blockDim.x + threadIdx.x;
    if (e >= nE) return;
    int s, d;
    if (g_is64) {
        const long long* p = (const long long*)ei;
        s = (int)p[e]; d = (int)p[nE + e];
    } else {
        const int* p = (const int*)ei;
        s = p[e]; d = p[nE + e];
    }
    int pos = atomicAdd(&g_cur[d], 1);
    g_srcs[pos] = s;
}

// ---------------------------------------------------------------------------
// GEMM1 via wmma v3: BOTH operands staged in smem. x loaded coalesced as
// float4 and converted to fp16 inline (k_xh kernel removed entirely).
// Block: 256 threads = 8 warps, tile 64 rows x 128 cols.
// Dynamic smem: W (128x136 half) + A (64x136 half) = 52.2 KB.
// Epilogue reuses smem as fp32 stage.
// ---------------------------------------------------------------------------
#define WPITCH 136
#define G1_W_HALFS (128 * WPITCH)
#define G1_A_HALFS (64 * WPITCH)
#define G1_SMEM ((G1_W_HALFS + G1_A_HALFS) * 2)

__global__ void __launch_bounds__(256)
k_gemm1(const float* __restrict__ x, const float* __restrict__ b) {
    extern __shared__ __align__(16) __half sm[];
    __half* Wm = sm;
    __half* Am = sm + G1_W_HALFS;

    int tid = threadIdx.x;
    int w = tid >> 5;
    int lane = tid & 31;
    int warpRow = w & 3;
    int warpColHalf = w >> 2;             // 0: y1 cols, 1: self cols
    int rowBase = blockIdx.x * 64 + warpRow * 16;
    int colBase = warpColHalf * 64;

    // cooperative load of W (128x128 halfs) into padded smem
    {
        const __half2* src = (const __half2*)g_w1h;
        for (int i = tid; i < 128 * 64; i += 256) {
            int row = i >> 6;
            int c2 = i & 63;
            *(__half2*)&Wm[row * WPITCH + c2 * 2] = src[row * 64 + c2];
        }
    }
    // cooperative load+convert of A tile (64 rows x 128 floats), coalesced
    {
        for (int i = tid; i < 64 * 32; i += 256) {
            int row = i >> 5;            // 0..63
            int q = i & 31;              // float4 slot -> cols q*4..q*4+3
            int grow = blockIdx.x * 64 + row;
            float4 v;
            if (grow < NN) v = __ldg((const float4*)(x + (size_t)grow * DD + q * 4));
            else           v = make_float4(0.f, 0.f, 0.f, 0.f);
            *(__half2*)&Am[row * WPITCH + q * 4]     = __floats2half2_rn(v.x, v.y);
            *(__half2*)&Am[row * WPITCH + q * 4 + 2] = __floats2half2_rn(v.z, v.w);
        }
    }
    __syncthreads();

    wmma::fragment<wmma::accumulator, 16, 16, 16, float> c[4];
    #pragma unroll
    for (int j = 0; j < 4; ++j) wmma::fill_fragment(c[j], 0.0f);

    const __half* arow = Am + warpRow * 16 * WPITCH;
    #pragma unroll 1
    for (int k = 0; k < 128; k += 16) {
        wmma::fragment<wmma::matrix_a, 16, 16, 16, __half, wmma::row_major> a;
        wmma::load_matrix_sync(a, arow + k, WPITCH);
        #pragma unroll
        for (int j = 0; j < 4; ++j) {
            wmma::fragment<wmma::matrix_b, 16, 16, 16, __half, wmma::row_major> bf;
            wmma::load_matrix_sync(bf, &Wm[k * WPITCH + colBase + j * 16], WPITCH);
            wmma::mma_sync(c[j], a, bf, c[j]);
        }
    }
    __syncthreads();   // done reading smem; reuse as fp32 stage

    float* stage = (float*)sm;            // 8 warps x 16x64 fp32 = 32 KB
    float* mystage = stage + w * 16 * 64;
    #pragma unroll
    for (int j = 0; j < 4; ++j)
        wmma::store_matrix_sync(mystage + j * 16, c[j], 64, wmma::mem_row_major);
    __syncwarp();

    // epilogue: lane covers row r = lane>>1, cols ch..ch+31 of the 64-col half
    int r = lane >> 1;
    int ch = (lane & 1) * 32;
    int grow = rowBase + r;
    __half* dst = warpColHalf ? g_selfh : g_y1h;
    if (grow < NN) {
        #pragma unroll
        for (int cc = 0; cc < 32; cc += 2) {
            int col = ch + cc;
            float v0 = mystage[r * 64 + col];
            float v1 = mystage[r * 64 + col + 1];
            if (warpColHalf) {
                v0 += b[col];
                v1 += b[col + 1];
            }
            *(__half2*)(dst + (size_t)grow * HH + col) = __floats2half2_rn(v0, v1);
        }
    }
}

// ---------------------------------------------------------------------------
// agg1 + ReLU: h[n] = relu( invdeg * sum_{s} y1[s] + self[n] )
// warp per node, half2 lanes, fp32 accumulation.  (measured version)
// ---------------------------------------------------------------------------
__global__ void k_agg1(void) {
    int w = (blockIdx.x * blockDim.x + threadIdx.x) >> 5;
    int lane = threadIdx.x & 31;
    if (w >= NN) return;
    int beg = g_rowptr[w], n = g_cnt[w];
    const __half2* yb = (const __half2*)g_y1h;
    float2 a0 = make_float2(0.f, 0.f), a1 = make_float2(0.f, 0.f);
    int e = 0;
    for (; e + 1 < n; e += 2) {
        int s0 = g_srcs[beg + e];
        int s1 = g_srcs[beg + e + 1];
        float2 v0 = __half22float2(__ldg(yb + (size_t)s0 * 32 + lane));
        float2 v1 = __half22float2(__ldg(yb + (size_t)s1 * 32 + lane));
        a0.x += v0.x; a0.y += v0.y;
        a1.x += v1.x; a1.y += v1.y;
    }
    if (e < n) {
        int s0 = g_srcs[beg + e];
        float2 v0 = __half22float2(__ldg(yb + (size_t)s0 * 32 + lane));
        a0.x += v0.x; a0.y += v0.y;
    }
    float sc = g_invdeg[w];
    float2 s = __half22float2(((const __half2*)g_selfh)[(size_t)w * 32 + lane]);
    float2 o;
    o.x = fmaxf((a0.x + a1.x) * sc + s.x, 0.f);
    o.y = fmaxf((a0.y + a1.y) * sc + s.y, 0.f);
    ((__half2*)g_hh)[(size_t)w * 32 + lane] = __float22half2_rn(o);
}

// ---------------------------------------------------------------------------
// agg2: g_agg2[n] = invdeg * sum_{s} h[s]   (half2 gather, fp32 out)
// ---------------------------------------------------------------------------
__global__ void k_agg2(void) {
    int w = (blockIdx.x * blockDim.x + threadIdx.x) >> 5;
    int lane = threadIdx.x & 31;
    if (w >= NN) return;
    int beg = g_rowptr[w], n = g_cnt[w];
    const __half2* hb = (const __half2*)g_hh;
    float2 a0 = make_float2(0.f, 0.f), a1 = make_float2(0.f, 0.f);
    int e = 0;
    for (; e + 1 < n; e += 2) {
        int s0 = g_srcs[beg + e];
        int s1 = g_srcs[beg + e + 1];
        float2 v0 = __half22float2(__ldg(hb + (size_t)s0 * 32 + lane));
        float2 v1 = __half22float2(__ldg(hb + (size_t)s1 * 32 + lane));
        a0.x += v0.x; a0.y += v0.y;
        a1.x += v1.x; a1.y += v1.y;
    }
    if (e < n) {
        int s0 = g_srcs[beg + e];
        float2 v0 = __half22float2(__ldg(hb + (size_t)s0 * 32 + lane));
        a0.x += v0.x; a0.y += v0.y;
    }
    float sc = g_invdeg[w];
    float2 o;
    o.x = (a0.x + a1.x) * sc;
    o.y = (a0.y + a1.y) * sc;
    ((float2*)g_agg2)[(size_t)w * 32 + lane] = o;
}

// ---------------------------------------------------------------------------
// GEMM2 + fused log_softmax, persistent grid-stride, packed f32x2.
// (measured version)
// ---------------------------------------------------------------------------
__global__ void __launch_bounds__(256)
k_gemm2(const float* __restrict__ Wl,
        const float* __restrict__ Wr,
        const float* __restrict__ b,
        float* __restrict__ out) {
    __shared__ float2 sW[64 * 40];
    __shared__ float sb[40];
    int tid = threadIdx.x;
    for (int i = tid; i < 64 * 40; i += blockDim.x)
        sW[i] = make_float2(Wl[i], Wr[i]);
    if (tid < 40) sb[tid] = b[tid];
    __syncthreads();

    int lane = tid & 31;
    bool lo8 = (lane < 8);
    int gwarp = (blockIdx.x * blockDim.x + tid) >> 5;
    int nwarps = (gridDim.x * blockDim.x) >> 5;

    for (int w = gwarp; w < NN; w += nwarps) {
        const float* ag = g_agg2 + (size_t)w * HH;
        float a0 = ag[lane], a1 = ag[lane + 32];
        float2 hf = __half22float2(((const __half2*)g_hh)[(size_t)w * 32 + lane]);
        float hlo = hf.x, hhi = hf.y;   // features 2*lane, 2*lane+1

        u64 acc0 = 0, acc1 = 0;
        #pragma unroll
        for (int f = 0; f < 64; ++f) {
            float av = __shfl_sync(0xffffffffu, (f < 32) ? a0 : a1, f & 31);
            float hv = __shfl_sync(0xffffffffu, (f & 1) ? hhi : hlo, f >> 1);
            u64 p = pack2(av, hv);
            fma2(acc0, p, *(const u64*)&sW[f * 40 + lane]);
            if (lo8) fma2(acc1, p, *(const u64*)&sW[f * 40 + 32 + lane]);
        }

        float u0, v0, u1, v1;
        unpack2(acc0, u0, v0);
        unpack2(acc1, u1, v1);
        float z0 = u0 + v0 + sb[lane];
        float z1 = lo8 ? (u1 + v1 + sb[32 + lane]) : -INFINITY;

        float m = fmaxf(z0, z1);
        #pragma unroll
        for (int o = 16; o; o >>= 1) m = fmaxf(m, __shfl_xor_sync(0xffffffffu, m, o));
        float e = expf(z0 - m) + (lo8 ? expf(z1 - m) : 0.f);
        #pragma unroll
        for (int o = 16; o; o >>= 1) e += __shfl_xor_sync(0xffffffffu, e, o);
        float lse = logf(e) + m;

        out[(size_t)w * CC + lane] = z0 - lse;
        if (lo8) out[(size_t)w * CC + 32 + lane] = z1 - lse;
    }
}

// ---------------------------------------------------------------------------
extern "C" void kernel_launch(void* const* d_in, const int* in_sizes, int n_in,
                              void* d_out, int out_size) {
    const float* x   = (const float*)d_in[0];
    const void*  ei  = d_in[1];
    const float* W1l = (const float*)d_in[2];
    const float* W1r = (const float*)d_in[3];
    const float* b1  = (const float*)d_in[4];
    const float* W2l = (const float*)d_in[5];
    const float* W2r = (const float*)d_in[6];
    const float* b2  = (const float*)d_in[7];
    float* out = (float*)d_out;

    int nE = in_sizes[1] / 2;
    int eBlocks = (nE + 255) / 256;
    int nWarpBlocks = (NN * 32 + 255) / 256;

    // dynamic smem for gemm1 (idempotent; host-side, capture-safe)
    cudaFuncSetAttribute(k_gemm1, cudaFuncAttributeMaxDynamicSharedMemorySize,
                         G1_SMEM);

    k_detzero<<<(NN + 255) / 256, 256>>>(ei);            // 1
    k_wh<<<64, 256>>>(W1l, W1r);                         // 2
    k_hist<<<eBlocks, 256>>>(ei, nE);                    // 3
    k_gemm1<<<NPAD / 64, 256, G1_SMEM>>>(x, b1);         // 4 <- ncu window
    k_scan1<<<NB, 256>>>();                              // 5
    k_scan23<<<NB, 256>>>();                             // 6
    k_fill<<<eBlocks, 256>>>(ei, nE);                    // 7
    k_agg1<<<nWarpBlocks, 256>>>();                      // 8
    k_agg2<<<nWarpBlocks, 256>>>();                      // 9
    k_gemm2<<<1184, 256>>>(W2l, W2r, b2, out);           // 10 persistent
}